// round 14
// baseline (speedup 1.0000x reference)
#include <cuda_runtime.h>
#include <cuda_fp16.h>
#include <cuda_fp8.h>
#include <cstdint>

#define EMBED   2048
#define NHEAD   32
#define HD      64
#define BATCH   2
#define SEQ     2048
#define MROWS   (BATCH*SEQ)      // 4096

// --- GEMM tiling: CTA 128x128, 8 warps (2x4), warp tile 64x32, 2 CTA/SM ---
#define TM      128
#define TN      128
#define ROWB    144
#define A_BYTES (TM*ROWB)        // 18432
#define B_BYTES (TN*ROWB)        // 18432
#define STAGE_BYTES (A_BYTES + B_BYTES)   // 36864
#define GSMEM   (3*STAGE_BYTES)           // 110592

#define WSCALE  64.0f            // fp8 weight pre-scale

// Scratch (device globals: no runtime allocation allowed)
__device__ __align__(16) __half  g_xh[(size_t)MROWS*EMBED];    // x fp16
__device__ __align__(16) uint8_t g_x8[(size_t)MROWS*EMBED];    // x e4m3
__device__ __align__(16) __half  g_qb[(size_t)MROWS*EMBED];    // Q fp16, pre-scaled 1/128
__device__ __align__(16) __half  g_kb[(size_t)MROWS*EMBED];    // K fp16
__device__ __align__(16) __half  g_vb[(size_t)MROWS*EMBED];    // V fp16
__device__ __align__(16) __half  g_ctx[(size_t)MROWS*EMBED];   // ctx fp16
__device__ __align__(16) uint8_t g_wq8[(size_t)EMBED*EMBED];   // Wq*64 e4m3
__device__ __align__(16) uint8_t g_wk8[(size_t)EMBED*EMBED];   // Wk*64 e4m3
__device__ __align__(16) __half  g_wv[(size_t)EMBED*EMBED];
__device__ __align__(16) __half  g_wo[(size_t)EMBED*EMBED];

// ---------------------------------------------------------------------------
__device__ __forceinline__ uint32_t smem_u32(const void* p) {
    uint32_t a;
    asm("{ .reg .u64 t; cvta.to.shared.u64 t, %1; cvt.u32.u64 %0, t; }"
        : "=r"(a) : "l"(p));
    return a;
}
#define SWZ(x) ((x) ^ (((x) >> 3) & 0x70))

#define LDSM_X4(r, addr) \
    asm volatile("ldmatrix.sync.aligned.m8n8.x4.shared.b16 {%0,%1,%2,%3}, [%4];" \
        : "=r"((r)[0]), "=r"((r)[1]), "=r"((r)[2]), "=r"((r)[3]) : "r"(addr))
#define LDSM_X4T(r, addr) \
    asm volatile("ldmatrix.sync.aligned.m8n8.x4.trans.shared.b16 {%0,%1,%2,%3}, [%4];" \
        : "=r"((r)[0]), "=r"((r)[1]), "=r"((r)[2]), "=r"((r)[3]) : "r"(addr))

#define MMA16816(d, a, b0, b1) \
    asm volatile("mma.sync.aligned.m16n8k16.row.col.f32.f16.f16.f32 " \
        "{%0,%1,%2,%3}, {%4,%5,%6,%7}, {%8,%9}, {%0,%1,%2,%3};" \
        : "+f"((d)[0]), "+f"((d)[1]), "+f"((d)[2]), "+f"((d)[3]) \
        : "r"((a)[0]), "r"((a)[1]), "r"((a)[2]), "r"((a)[3]), "r"(b0), "r"(b1))

#define MMAFP8(d, a, b0, b1) \
    asm volatile("mma.sync.aligned.m16n8k32.row.col.f32.e4m3.e4m3.f32 " \
        "{%0,%1,%2,%3}, {%4,%5,%6,%7}, {%8,%9}, {%0,%1,%2,%3};" \
        : "+f"((d)[0]), "+f"((d)[1]), "+f"((d)[2]), "+f"((d)[3]) \
        : "r"((a)[0]), "r"((a)[1]), "r"((a)[2]), "r"((a)[3]), "r"(b0), "r"(b1))

__device__ __forceinline__ uint32_t packh(float x, float y) {
    __half2 t = __floats2half2_rn(x, y);
    return *reinterpret_cast<uint32_t*>(&t);
}
__device__ __forceinline__ uint32_t pack8(float a, float b, float c, float d) {
    __nv_fp8x4_e4m3 p(make_float4(a, b, c, d));
    return *reinterpret_cast<uint32_t*>(&p);
}

// ---------------------------------------------------------------------------
// Fused conversions:
//  seg x : fp32 -> fp16 (xh) AND e4m3 (x8)
//  seg wq/wk : fp32*64 -> e4m3
//  seg wv/wo : fp32 -> fp16
// ---------------------------------------------------------------------------
#define XT4 ((MROWS*EMBED)/4)           // 2097152
#define WT4 ((EMBED*EMBED)/4)           // 1048576
#define CONV_TASKS (XT4 + 4*WT4)

__global__ void conv_all(const float* __restrict__ x,
                         const float* __restrict__ wq, const float* __restrict__ wk,
                         const float* __restrict__ wv, const float* __restrict__ wo,
                         __half* __restrict__ xh, uint8_t* __restrict__ x8,
                         uint8_t* __restrict__ oq8, uint8_t* __restrict__ ok8,
                         __half* __restrict__ ov, __half* __restrict__ oo)
{
    int idx = blockIdx.x * 256 + threadIdx.x;
    if (idx >= CONV_TASKS) return;
    if (idx < XT4) {
        size_t rel = (size_t)idx;
        float4 v = *(const float4*)(x + rel * 4);
        uint2 o;
        o.x = packh(v.x, v.y);
        o.y = packh(v.z, v.w);
        *(uint2*)(xh + rel * 4) = o;
        *(uint32_t*)(x8 + rel * 4) = pack8(v.x, v.y, v.z, v.w);
    } else {
        int j = idx - XT4;
        int seg = j >> 20;                 // WT4 = 1<<20
        size_t rel = (size_t)(j & (WT4 - 1));
        if (seg < 2) {
            const float* src = (seg == 0) ? wq : wk;
            uint8_t* dst = (seg == 0) ? oq8 : ok8;
            float4 v = *(const float4*)(src + rel * 4);
            *(uint32_t*)(dst + rel * 4) =
                pack8(v.x * WSCALE, v.y * WSCALE, v.z * WSCALE, v.w * WSCALE);
        } else {
            const float* src = (seg == 2) ? wv : wo;
            __half* dst = (seg == 2) ? ov : oo;
            float4 v = *(const float4*)(src + rel * 4);
            uint2 o;
            o.x = packh(v.x, v.y);
            o.y = packh(v.z, v.w);
            *(uint2*)(dst + rel * 4) = o;
        }
    }
}

// ---------------------------------------------------------------------------
// fp8 GEMM (Q,K projections): z selects {Wq,Wk}. C = (A8 @ B8^T)/64 + bias,
// fp16 out, Q additionally scaled 1/128. Same pipeline as fp16 kernel,
// chunk = 128 bytes of K (= 128 fp8 elems), nchunk = 16.
// ---------------------------------------------------------------------------
__global__ __launch_bounds__(256, 2)
void gemm_fp8(const uint8_t* __restrict__ A,
              const uint8_t* __restrict__ B0, const uint8_t* __restrict__ B1,
              const float* __restrict__ bi0, const float* __restrict__ bi1,
              __half* __restrict__ C0, __half* __restrict__ C1)
{
    const int z = blockIdx.z;
    const uint8_t* B  = (z == 0) ? B0 : B1;
    const float* bias = (z == 0) ? bi0 : bi1;
    __half* C         = (z == 0) ? C0 : C1;
    const float qs    = (z == 0) ? (1.0f / 128.0f) : 1.0f;
    const float inv64 = 1.0f / WSCALE;

    extern __shared__ char dsm[];
    const uint32_t sbase0 = smem_u32(dsm);
    const int tid    = threadIdx.x;
    const int warp   = tid >> 5;
    const int lane   = tid & 31;
    const int warp_m = warp >> 2;
    const int warp_n = warp & 3;
    const int tm0    = blockIdx.y * TM;
    const int tn0    = blockIdx.x * TN;
    const int nchunk = 16;               // 2048 B / 128 B

    const int g  = lane >> 3;
    const int lr = lane & 7;
    uint32_t aoff[4], boff[2];
#pragma unroll
    for (int mi = 0; mi < 4; mi++)
        aoff[mi] = (uint32_t)((warp_m * 64 + mi * 16 + (g & 1) * 8 + lr) * ROWB
                              + (g >> 1) * 16);
#pragma unroll
    for (int nj = 0; nj < 2; nj++)
        boff[nj] = (uint32_t)(A_BYTES
                              + (warp_n * 32 + nj * 16 + (g & 1) * 8 + lr) * ROWB
                              + (g >> 1) * 16);

    float acc[4][4][4];
#pragma unroll
    for (int mi = 0; mi < 4; mi++)
#pragma unroll
        for (int n8 = 0; n8 < 4; n8++)
#pragma unroll
            for (int e = 0; e < 4; e++) acc[mi][n8][e] = 0.0f;

#define LOAD_CHUNK8(ci) do {                                                     \
    uint32_t sb_ = sbase0 + ((ci) % 3) * STAGE_BYTES;                            \
    int kc0_ = (ci) * 128;                                                       \
    _Pragma("unroll")                                                            \
    for (int j_ = 0; j_ < 4; j_++) {                                             \
        int t_ = tid + j_ * 256;                                                 \
        int r_ = t_ >> 3, c_ = t_ & 7;                                           \
        const uint8_t* src_ = A + (size_t)(tm0 + r_) * EMBED + kc0_ + c_*16;     \
        uint32_t dst_ = sb_ + r_ * ROWB + c_ * 16;                               \
        asm volatile("cp.async.cg.shared.global [%0], [%1], 16;"                 \
                     :: "r"(dst_), "l"(src_));                                   \
    }                                                                            \
    _Pragma("unroll")                                                            \
    for (int j_ = 0; j_ < 4; j_++) {                                             \
        int t_ = tid + j_ * 256;                                                 \
        int r_ = t_ >> 3, c_ = t_ & 7;                                           \
        const uint8_t* src_ = B + (size_t)(tn0 + r_) * EMBED + kc0_ + c_*16;     \
        uint32_t dst_ = sb_ + A_BYTES + r_ * ROWB + c_ * 16;                     \
        asm volatile("cp.async.cg.shared.global [%0], [%1], 16;"                 \
                     :: "r"(dst_), "l"(src_));                                   \
    }                                                                            \
    asm volatile("cp.async.commit_group;" ::: "memory");                         \
} while (0)

#define LOAD_FRAGS8(buf, sb, ks) do {                                            \
    _Pragma("unroll")                                                            \
    for (int mi_ = 0; mi_ < 4; mi_++)                                            \
        LDSM_X4(aF[buf][mi_], (sb) + aoff[mi_] + (ks) * 32);                     \
    _Pragma("unroll")                                                            \
    for (int nj_ = 0; nj_ < 2; nj_++)                                            \
        LDSM_X4(bF[buf][nj_], (sb) + boff[nj_] + (ks) * 32);                     \
} while (0)

#define MMA_BLOCK8(buf) do {                                                     \
    _Pragma("unroll")                                                            \
    for (int mi_ = 0; mi_ < 4; mi_++)                                            \
        _Pragma("unroll")                                                        \
        for (int n8_ = 0; n8_ < 4; n8_++)                                        \
            MMAFP8(acc[mi_][n8_], aF[buf][mi_],                                  \
                   bF[buf][n8_ >> 1][n8_ & 1],                                   \
                   bF[buf][n8_ >> 1][2 + (n8_ & 1)]);                            \
} while (0)

    uint32_t aF[2][4][4], bF[2][2][4];

    LOAD_CHUNK8(0);
    LOAD_CHUNK8(1);
    asm volatile("cp.async.wait_group 1;" ::: "memory");
    __syncthreads();
    LOAD_FRAGS8(0, sbase0, 0);

    for (int i = 0; i < nchunk; i++) {
        const uint32_t sb = sbase0 + (i % 3) * STAGE_BYTES;

        if (i + 2 < nchunk) LOAD_CHUNK8(i + 2);

        LOAD_FRAGS8(1, sb, 1);
        MMA_BLOCK8(0);
        LOAD_FRAGS8(0, sb, 2);
        MMA_BLOCK8(1);
        LOAD_FRAGS8(1, sb, 3);
        MMA_BLOCK8(0);

        if (i + 1 < nchunk) {
            asm volatile("cp.async.wait_group 1;" ::: "memory");
            __syncthreads();
            LOAD_FRAGS8(0, sbase0 + ((i + 1) % 3) * STAGE_BYTES, 0);
        }

        MMA_BLOCK8(1);
    }
#undef LOAD_CHUNK8
#undef LOAD_FRAGS8
#undef MMA_BLOCK8

    const int qr = lane >> 2;
    const int qc = (lane & 3) * 2;
#pragma unroll
    for (int mi = 0; mi < 4; mi++) {
        int row = tm0 + warp_m * 64 + mi * 16 + qr;
#pragma unroll
        for (int n8 = 0; n8 < 4; n8++) {
            int col = tn0 + warp_n * 32 + n8 * 8 + qc;
            float b0 = __ldg(bias + col);
            float b1 = __ldg(bias + col + 1);
            *(uint32_t*)(C + (size_t)row * EMBED + col) =
                packh(fmaf(acc[mi][n8][0], inv64, b0) * qs,
                      fmaf(acc[mi][n8][1], inv64, b1) * qs);
            *(uint32_t*)(C + (size_t)(row + 8) * EMBED + col) =
                packh(fmaf(acc[mi][n8][2], inv64, b0) * qs,
                      fmaf(acc[mi][n8][3], inv64, b1) * qs);
        }
    }
}

// ---------------------------------------------------------------------------
// fp16 HMMA GEMM (R12 config): MODE 0: fp16 out (scale), MODE 1: fp32 out.
// ---------------------------------------------------------------------------
template<int MODE>
__global__ __launch_bounds__(256, 2)
void gemm_tpl(const __half* __restrict__ A, const __half* __restrict__ B,
              const float* __restrict__ bias,
              __half* __restrict__ C, float* __restrict__ Cf, float scale)
{
    extern __shared__ char dsm[];
    const uint32_t sbase0 = smem_u32(dsm);
    const int tid    = threadIdx.x;
    const int warp   = tid >> 5;
    const int lane   = tid & 31;
    const int warp_m = warp >> 2;
    const int warp_n = warp & 3;
    const int tm0    = blockIdx.y * TM;
    const int tn0    = blockIdx.x * TN;
    const int nchunk = 32;               // 2048 / 64

    const int g  = lane >> 3;
    const int lr = lane & 7;
    uint32_t aoff[4], boff[2];
#pragma unroll
    for (int mi = 0; mi < 4; mi++)
        aoff[mi] = (uint32_t)((warp_m * 64 + mi * 16 + (g & 1) * 8 + lr) * ROWB
                              + (g >> 1) * 16);
#pragma unroll
    for (int nj = 0; nj < 2; nj++)
        boff[nj] = (uint32_t)(A_BYTES
                              + (warp_n * 32 + nj * 16 + (g & 1) * 8 + lr) * ROWB
                              + (g >> 1) * 16);

    float acc[4][4][4];
#pragma unroll
    for (int mi = 0; mi < 4; mi++)
#pragma unroll
        for (int n8 = 0; n8 < 4; n8++)
#pragma unroll
            for (int e = 0; e < 4; e++) acc[mi][n8][e] = 0.0f;

#define LOAD_CHUNK(ci) do {                                                      \
    uint32_t sb_ = sbase0 + ((ci) % 3) * STAGE_BYTES;                            \
    int kc0_ = (ci) * 64;                                                        \
    _Pragma("unroll")                                                            \
    for (int j_ = 0; j_ < 4; j_++) {                                             \
        int t_ = tid + j_ * 256;                                                 \
        int r_ = t_ >> 3, c_ = t_ & 7;                                           \
        const __half* src_ = A + (size_t)(tm0 + r_) * EMBED + kc0_ + c_*8;       \
        uint32_t dst_ = sb_ + r_ * ROWB + c_ * 16;                               \
        asm volatile("cp.async.cg.shared.global [%0], [%1], 16;"                 \
                     :: "r"(dst_), "l"(src_));                                   \
    }                                                                            \
    _Pragma("unroll")                                                            \
    for (int j_ = 0; j_ < 4; j_++) {                                             \
        int t_ = tid + j_ * 256;                                                 \
        int r_ = t_ >> 3, c_ = t_ & 7;                                           \
        const __half* src_ = B + (size_t)(tn0 + r_) * EMBED + kc0_ + c_*8;       \
        uint32_t dst_ = sb_ + A_BYTES + r_ * ROWB + c_ * 16;                     \
        asm volatile("cp.async.cg.shared.global [%0], [%1], 16;"                 \
                     :: "r"(dst_), "l"(src_));                                   \
    }                                                                            \
    asm volatile("cp.async.commit_group;" ::: "memory");                         \
} while (0)

#define LOAD_FRAGS(buf, sb, ks) do {                                             \
    _Pragma("unroll")                                                            \
    for (int mi_ = 0; mi_ < 4; mi_++)                                            \
        LDSM_X4(aF[buf][mi_], (sb) + aoff[mi_] + (ks) * 32);                     \
    _Pragma("unroll")                                                            \
    for (int nj_ = 0; nj_ < 2; nj_++)                                            \
        LDSM_X4(bF[buf][nj_], (sb) + boff[nj_] + (ks) * 32);                     \
} while (0)

#define MMA_BLOCK(buf) do {                                                      \
    _Pragma("unroll")                                                            \
    for (int mi_ = 0; mi_ < 4; mi_++)                                            \
        _Pragma("unroll")                                                        \
        for (int n8_ = 0; n8_ < 4; n8_++)                                        \
            MMA16816(acc[mi_][n8_], aF[buf][mi_],                                \
                     bF[buf][n8_ >> 1][n8_ & 1],                                 \
                     bF[buf][n8_ >> 1][2 + (n8_ & 1)]);                          \
} while (0)

    uint32_t aF[2][4][4], bF[2][2][4];

    LOAD_CHUNK(0);
    LOAD_CHUNK(1);
    asm volatile("cp.async.wait_group 1;" ::: "memory");
    __syncthreads();
    LOAD_FRAGS(0, sbase0, 0);

    for (int i = 0; i < nchunk; i++) {
        const uint32_t sb = sbase0 + (i % 3) * STAGE_BYTES;

        if (i + 2 < nchunk) LOAD_CHUNK(i + 2);

        LOAD_FRAGS(1, sb, 1);
        MMA_BLOCK(0);
        LOAD_FRAGS(0, sb, 2);
        MMA_BLOCK(1);
        LOAD_FRAGS(1, sb, 3);
        MMA_BLOCK(0);

        if (i + 1 < nchunk) {
            asm volatile("cp.async.wait_group 1;" ::: "memory");
            __syncthreads();
            LOAD_FRAGS(0, sbase0 + ((i + 1) % 3) * STAGE_BYTES, 0);
        }

        MMA_BLOCK(1);
    }
#undef LOAD_CHUNK
#undef LOAD_FRAGS
#undef MMA_BLOCK

    const int qr = lane >> 2;
    const int qc = (lane & 3) * 2;
#pragma unroll
    for (int mi = 0; mi < 4; mi++) {
        int row = tm0 + warp_m * 64 + mi * 16 + qr;
#pragma unroll
        for (int n8 = 0; n8 < 4; n8++) {
            int col = tn0 + warp_n * 32 + n8 * 8 + qc;
            float b0 = __ldg(bias + col);
            float b1 = __ldg(bias + col + 1);
            if (MODE == 0) {
                *(uint32_t*)(C + (size_t)row * EMBED + col) =
                    packh((acc[mi][n8][0] + b0) * scale,
                          (acc[mi][n8][1] + b1) * scale);
                *(uint32_t*)(C + (size_t)(row + 8) * EMBED + col) =
                    packh((acc[mi][n8][2] + b0) * scale,
                          (acc[mi][n8][3] + b1) * scale);
            } else {
                float2 o0 = { acc[mi][n8][0] + b0, acc[mi][n8][1] + b1 };
                float2 o1 = { acc[mi][n8][2] + b0, acc[mi][n8][3] + b1 };
                *(float2*)(Cf + (size_t)row * EMBED + col) = o0;
                *(float2*)(Cf + (size_t)(row + 8) * EMBED + col) = o1;
            }
        }
    }
}

// ---------------------------------------------------------------------------
// Tensor-core causal flash attention (fp16), max-free softmax (unchanged).
// ---------------------------------------------------------------------------
#define AKV       64
#define AQ_BYTES  16384
#define ASTAGE    16384
#define ATTN_SMEM (AQ_BYTES + 2*ASTAGE)

__global__ __launch_bounds__(256, 2)
void attn_tc(const __half* __restrict__ Qg, const __half* __restrict__ Kg,
             const __half* __restrict__ Vg, __half* __restrict__ Ctx)
{
    extern __shared__ char smbuf[];
    const uint32_t sbase = smem_u32(smbuf);
    const int tid  = threadIdx.x;
    const int lane = tid & 31;
    const int w    = tid >> 5;
    const int qt   = gridDim.x - 1 - blockIdx.x;
    const int bh   = blockIdx.y;
    const int b    = bh >> 5;
    const int h    = bh & 31;
    const int q0   = qt * 128;

    const size_t rowbase = (size_t)(b * SEQ);
    const __half* Qb = Qg + (rowbase + q0) * EMBED + h * HD;
    const __half* Kb = Kg + rowbase * EMBED + h * HD;
    const __half* Vb = Vg + rowbase * EMBED + h * HD;

#pragma unroll
    for (int t = 0; t < 4; t++) {
        int task = tid + t * 256;
        int r = task >> 3, c = task & 7;
        uint32_t dst = sbase + SWZ(r * 128 + c * 16);
        const __half* src = Qb + (size_t)r * EMBED + c * 8;
        asm volatile("cp.async.cg.shared.global [%0], [%1], 16;"
                     :: "r"(dst), "l"(src));
    }

#define LOADKV(jt_, st_) do {                                                     \
    uint32_t sb_ = sbase + AQ_BYTES + (st_) * ASTAGE;                             \
    _Pragma("unroll")                                                             \
    for (int t_ = 0; t_ < 4; t_++) {                                              \
        int task_ = tid + t_ * 256;                                               \
        int arr_  = task_ >> 9;                                                   \
        int idx_  = task_ & 511;                                                  \
        int r_ = idx_ >> 3, c_ = idx_ & 7;                                        \
        const __half* s_ = (arr_ == 0 ? Kb : Vb)                                  \
                           + (size_t)((jt_) * AKV + r_) * EMBED + c_ * 8;         \
        uint32_t d_ = sb_ + arr_ * 8192 + SWZ(r_ * 128 + c_ * 16);                \
        asm volatile("cp.async.cg.shared.global [%0], [%1], 16;"                  \
                     :: "r"(d_), "l"(s_));                                        \
    }                                                                             \
    asm volatile("cp.async.commit_group;" ::: "memory");                          \
} while (0)

    LOADKV(0, 0);

    float l0 = 0.0f, l1 = 0.0f;
    float oacc[8][4];
#pragma unroll
    for (int j = 0; j < 8; j++)
#pragma unroll
        for (int e = 0; e < 4; e++) oacc[j][e] = 0.0f;
    uint32_t aq[4][4];

    const int la7 = lane & 7, lb3 = (lane >> 3) & 1, lb4 = (lane >> 4) & 1;
    const int qrow = w * 16 + la7 + lb3 * 8, qcolb = lb4 * 16;
    const int krow = la7 + lb4 * 8,          kcolb = lb3 * 16;
    const int vrow = la7 + lb3 * 8,          vcolb = lb4 * 16;
    const int wrow_min = q0 + w * 16;
    const int wrow_max = wrow_min + 15;
    const int ntiles = 2 * qt + 2;

    for (int jt = 0; jt < ntiles; jt++) {
        if (jt + 1 < ntiles) {
            LOADKV(jt + 1, (jt + 1) & 1);
            asm volatile("cp.async.wait_group 1;" ::: "memory");
        } else {
            asm volatile("cp.async.wait_group 0;" ::: "memory");
        }
        __syncthreads();

        if (jt == 0) {
#pragma unroll
            for (int ks = 0; ks < 4; ks++)
                LDSM_X4(aq[ks], sbase + SWZ(qrow * 128 + ks * 32 + qcolb));
        }

        const uint32_t kst = sbase + AQ_BYTES + (jt & 1) * ASTAGE;
        if (jt * AKV <= wrow_max) {
            float sa[8][4];
#pragma unroll
            for (int j = 0; j < 8; j++)
#pragma unroll
                for (int e = 0; e < 4; e++) sa[j][e] = 0.0f;
#pragma unroll
            for (int ks = 0; ks < 4; ks++)
#pragma unroll
                for (int jp = 0; jp < 4; jp++) {
                    uint32_t kf[4];
                    LDSM_X4(kf, kst + SWZ((jp * 16 + krow) * 128 + ks * 32 + kcolb));
                    MMA16816(sa[2 * jp],     aq[ks], kf[0], kf[1]);
                    MMA16816(sa[2 * jp + 1], aq[ks], kf[2], kf[3]);
                }

            if (jt * AKV + 63 > wrow_min) {
#pragma unroll
                for (int j = 0; j < 8; j++) {
                    int colb = jt * AKV + j * 8 + 2 * (lane & 3);
                    int r0g  = wrow_min + (lane >> 2);
#pragma unroll
                    for (int e = 0; e < 4; e++) {
                        int col = colb + (e & 1);
                        int row = r0g + (e >> 1) * 8;
                        if (col > row) sa[j][e] = -1e30f;
                    }
                }
            }

            float rs0 = 0.0f, rs1 = 0.0f;
#pragma unroll
            for (int j = 0; j < 8; j++) {
                sa[j][0] = __expf(sa[j][0]);
                sa[j][1] = __expf(sa[j][1]);
                sa[j][2] = __expf(sa[j][2]);
                sa[j][3] = __expf(sa[j][3]);
                rs0 += sa[j][0] + sa[j][1];
                rs1 += sa[j][2] + sa[j][3];
            }
            rs0 += __shfl_xor_sync(0xffffffffu, rs0, 1);
            rs0 += __shfl_xor_sync(0xffffffffu, rs0, 2);
            rs1 += __shfl_xor_sync(0xffffffffu, rs1, 1);
            rs1 += __shfl_xor_sync(0xffffffffu, rs1, 2);
            l0 += rs0;
            l1 += rs1;

#pragma unroll
            for (int t = 0; t < 4; t++) {
                uint32_t pa[4];
                pa[0] = packh(sa[2*t][0],   sa[2*t][1]);
                pa[1] = packh(sa[2*t][2],   sa[2*t][3]);
                pa[2] = packh(sa[2*t+1][0], sa[2*t+1][1]);
                pa[3] = packh(sa[2*t+1][2], sa[2*t+1][3]);
#pragma unroll
                for (int gg = 0; gg < 4; gg++) {
                    uint32_t vF[4];
                    uint32_t va = SWZ((t * 16 + vrow) * 128 + gg * 32 + vcolb);
                    LDSM_X4T(vF, kst + 8192 + va);
                    MMA16816(oacc[2*gg],   pa, vF[0], vF[1]);
                    MMA16816(oacc[2*gg+1], pa, vF[2], vF[3]);
                }
            }
        }
        __syncthreads();
    }
#undef LOADKV

    float inv0 = 1.0f / l0, inv1 = 1.0f / l1;
    size_t grow0 = rowbase + q0 + w * 16 + (lane >> 2);
    __half* base0 = Ctx + grow0 * EMBED + h * HD + 2 * (lane & 3);
    __half* base1 = base0 + (size_t)8 * EMBED;
#pragma unroll
    for (int j = 0; j < 8; j++) {
        *(uint32_t*)(base0 + j * 8) = packh(oacc[j][0] * inv0, oacc[j][1] * inv0);
        *(uint32_t*)(base1 + j * 8) = packh(oacc[j][2] * inv1, oacc[j][3] * inv1);
    }
}

// ---------------------------------------------------------------------------
extern "C" void kernel_launch(void* const* d_in, const int* in_sizes, int n_in,
                              void* d_out, int out_size)
{
    const float* x  = (const float*)d_in[0];
    const float* Wq = (const float*)d_in[1];
    const float* bq = (const float*)d_in[2];
    const float* Wk = (const float*)d_in[3];
    const float* bk = (const float*)d_in[4];
    const float* Wv = (const float*)d_in[5];
    const float* bv = (const float*)d_in[6];
    const float* Wo = (const float*)d_in[7];
    const float* bo = (const float*)d_in[8];
    float* out = (float*)d_out;

    __half *xh, *qb, *kb, *vb, *ctx, *wv, *wo;
    uint8_t *x8, *wq8, *wk8;
    cudaGetSymbolAddress((void**)&xh,  g_xh);
    cudaGetSymbolAddress((void**)&x8,  g_x8);
    cudaGetSymbolAddress((void**)&qb,  g_qb);
    cudaGetSymbolAddress((void**)&kb,  g_kb);
    cudaGetSymbolAddress((void**)&vb,  g_vb);
    cudaGetSymbolAddress((void**)&ctx, g_ctx);
    cudaGetSymbolAddress((void**)&wq8, g_wq8);
    cudaGetSymbolAddress((void**)&wk8, g_wk8);
    cudaGetSymbolAddress((void**)&wv,  g_wv);
    cudaGetSymbolAddress((void**)&wo,  g_wo);

    cudaFuncSetAttribute(attn_tc, cudaFuncAttributeMaxDynamicSharedMemorySize,
                         ATTN_SMEM);
    cudaFuncSetAttribute(gemm_fp8, cudaFuncAttributeMaxDynamicSharedMemorySize,
                         GSMEM);
    cudaFuncSetAttribute(gemm_tpl<0>, cudaFuncAttributeMaxDynamicSharedMemorySize,
                         GSMEM);
    cudaFuncSetAttribute(gemm_tpl<1>, cudaFuncAttributeMaxDynamicSharedMemorySize,
                         GSMEM);

    conv_all<<<(CONV_TASKS + 255) / 256, 256>>>(x, Wq, Wk, Wv, Wo,
                                                xh, x8, wq8, wk8, wv, wo);

    dim3 qkgrid(EMBED / TN, MROWS / TM, 2);      // (16, 32, 2)
    gemm_fp8<<<qkgrid, 256, GSMEM>>>(x8, wq8, wk8, bq, bk, qb, kb);

    dim3 vgrid(EMBED / TN, MROWS / TM);          // (16, 32)
    gemm_tpl<0><<<vgrid, 256, GSMEM>>>(xh, wv, bv, vb, nullptr, 1.0f);

    dim3 agrid(SEQ / 128, BATCH * NHEAD);        // (16, 64)
    attn_tc<<<agrid, 256, ATTN_SMEM>>>(qb, kb, vb, ctx);

    gemm_tpl<1><<<vgrid, 256, GSMEM>>>(ctx, wo, bo, nullptr, out, 1.0f);
}

// round 15
// speedup vs baseline: 1.1026x; 1.1026x over previous
#include <cuda_runtime.h>
#include <cuda_fp16.h>
#include <cstdint>

#define EMBED   2048
#define NHEAD   32
#define HD      64
#define BATCH   2
#define SEQ     2048
#define MROWS   (BATCH*SEQ)      // 4096

// --- GEMM tiling: CTA 128x128, 8 warps (2x4), warp tile 64x32 ---
#define TM      128
#define TN      128
#define KC      64
#define ROWB    144
#define A_BYTES (TM*ROWB)        // 18432
#define B_BYTES (TN*ROWB)        // 18432
#define STAGE_BYTES (A_BYTES + B_BYTES)   // 36864
#define GSMEM   (3*STAGE_BYTES)           // 110592 (2 CTAs/SM: 216KB)

// Scratch (device globals: no runtime allocation allowed)
__device__ __align__(16) __half g_xh[(size_t)MROWS*EMBED];    // x fp16
__device__ __align__(16) __half g_qb[(size_t)MROWS*EMBED];    // Q fp16, pre-scaled 1/128
__device__ __align__(16) __half g_kb[(size_t)MROWS*EMBED];    // K fp16
__device__ __align__(16) __half g_vb[(size_t)MROWS*EMBED];    // V fp16
__device__ __align__(16) __half g_ctx[(size_t)MROWS*EMBED];   // ctx fp16 (from attn)
__device__ __align__(16) __half g_wq[(size_t)EMBED*EMBED];
__device__ __align__(16) __half g_wk[(size_t)EMBED*EMBED];
__device__ __align__(16) __half g_wv[(size_t)EMBED*EMBED];
__device__ __align__(16) __half g_wo[(size_t)EMBED*EMBED];

// ---------------------------------------------------------------------------
__device__ __forceinline__ uint32_t smem_u32(const void* p) {
    uint32_t a;
    asm("{ .reg .u64 t; cvta.to.shared.u64 t, %1; cvt.u32.u64 %0, t; }"
        : "=r"(a) : "l"(p));
    return a;
}
#define SWZ(x) ((x) ^ (((x) >> 3) & 0x70))

#define LDSM_X4(r, addr) \
    asm volatile("ldmatrix.sync.aligned.m8n8.x4.shared.b16 {%0,%1,%2,%3}, [%4];" \
        : "=r"((r)[0]), "=r"((r)[1]), "=r"((r)[2]), "=r"((r)[3]) : "r"(addr))
#define LDSM_X4T(r, addr) \
    asm volatile("ldmatrix.sync.aligned.m8n8.x4.trans.shared.b16 {%0,%1,%2,%3}, [%4];" \
        : "=r"((r)[0]), "=r"((r)[1]), "=r"((r)[2]), "=r"((r)[3]) : "r"(addr))

#define MMA16816(d, a, b0, b1) \
    asm volatile("mma.sync.aligned.m16n8k16.row.col.f32.f16.f16.f32 " \
        "{%0,%1,%2,%3}, {%4,%5,%6,%7}, {%8,%9}, {%0,%1,%2,%3};" \
        : "+f"((d)[0]), "+f"((d)[1]), "+f"((d)[2]), "+f"((d)[3]) \
        : "r"((a)[0]), "r"((a)[1]), "r"((a)[2]), "r"((a)[3]), "r"(b0), "r"(b1))

__device__ __forceinline__ uint32_t packh(float x, float y) {
    __half2 t = __floats2half2_rn(x, y);
    return *reinterpret_cast<uint32_t*>(&t);
}

// ---------------------------------------------------------------------------
// Fused fp32 -> fp16 conversion of x + 4 weights (float4 granularity).
// ---------------------------------------------------------------------------
#define XT4 ((MROWS*EMBED)/4)           // 2097152
#define WT4 ((EMBED*EMBED)/4)           // 1048576
#define CONV_TASKS (XT4 + 4*WT4)        // 6291456

__global__ void conv_all(const float* __restrict__ x,
                         const float* __restrict__ wq, const float* __restrict__ wk,
                         const float* __restrict__ wv, const float* __restrict__ wo,
                         __half* __restrict__ xh,
                         __half* __restrict__ oq, __half* __restrict__ ok,
                         __half* __restrict__ ov, __half* __restrict__ oo)
{
    int idx = blockIdx.x * 256 + threadIdx.x;
    if (idx >= CONV_TASKS) return;
    const float* src; __half* dst; size_t rel;
    if (idx < XT4) {
        src = x; dst = xh; rel = (size_t)idx;
    } else {
        int j = idx - XT4;
        int seg = j >> 20;                 // WT4 = 1<<20
        rel = (size_t)(j & (WT4 - 1));
        src = (seg == 0) ? wq : (seg == 1) ? wk : (seg == 2) ? wv : wo;
        dst = (seg == 0) ? oq : (seg == 1) ? ok : (seg == 2) ? ov : oo;
    }
    float4 v = *(const float4*)(src + rel * 4);
    uint2 o;
    o.x = packh(v.x, v.y);
    o.y = packh(v.z, v.w);
    *(uint2*)(dst + rel * 4) = o;
}

// ---------------------------------------------------------------------------
// HMMA fp16 GEMM (R12 config, unchanged):
//   MODE 0: fused QKV (z selects weight/bias/output, fp16 out, Q scaled)
//   MODE 1: out-proj (fp32 out)
// ---------------------------------------------------------------------------
template<int MODE>
__global__ __launch_bounds__(256, 2)
void gemm_tpl(const __half* __restrict__ A,
              const __half* __restrict__ B0, const __half* __restrict__ B1,
              const __half* __restrict__ B2,
              const float* __restrict__ bi0, const float* __restrict__ bi1,
              const float* __restrict__ bi2,
              __half* __restrict__ C0, __half* __restrict__ C1,
              __half* __restrict__ C2, float* __restrict__ Cf)
{
    const int z = (MODE == 0) ? blockIdx.z : 0;
    const __half* B   = (z == 0) ? B0 : (z == 1) ? B1 : B2;
    const float* bias = (z == 0) ? bi0 : (z == 1) ? bi1 : bi2;
    __half* C         = (z == 0) ? C0 : (z == 1) ? C1 : C2;
    const float scale = (MODE == 0 && z == 0) ? (1.0f / 128.0f) : 1.0f;

    extern __shared__ char dsm[];
    const uint32_t sbase0 = smem_u32(dsm);
    const int tid    = threadIdx.x;
    const int warp   = tid >> 5;
    const int lane   = tid & 31;
    const int warp_m = warp >> 2;
    const int warp_n = warp & 3;
    const int tm0    = blockIdx.y * TM;
    const int tn0    = blockIdx.x * TN;
    const int nchunk = EMBED / KC;       // 32

    const int g  = lane >> 3;
    const int lr = lane & 7;
    uint32_t aoff[4], boff[2];
#pragma unroll
    for (int mi = 0; mi < 4; mi++)
        aoff[mi] = (uint32_t)((warp_m * 64 + mi * 16 + (g & 1) * 8 + lr) * ROWB
                              + (g >> 1) * 16);
#pragma unroll
    for (int nj = 0; nj < 2; nj++)
        boff[nj] = (uint32_t)(A_BYTES
                              + (warp_n * 32 + nj * 16 + (g & 1) * 8 + lr) * ROWB
                              + (g >> 1) * 16);

    float acc[4][4][4];
#pragma unroll
    for (int mi = 0; mi < 4; mi++)
#pragma unroll
        for (int n8 = 0; n8 < 4; n8++)
#pragma unroll
            for (int e = 0; e < 4; e++) acc[mi][n8][e] = 0.0f;

#define LOAD_CHUNK(ci) do {                                                      \
    uint32_t sb_ = sbase0 + ((ci) % 3) * STAGE_BYTES;                            \
    int kc0_ = (ci) * KC;                                                        \
    _Pragma("unroll")                                                            \
    for (int j_ = 0; j_ < 4; j_++) {                                             \
        int t_ = tid + j_ * 256;                                                 \
        int r_ = t_ >> 3, c_ = t_ & 7;                                           \
        const __half* src_ = A + (size_t)(tm0 + r_) * EMBED + kc0_ + c_*8;       \
        uint32_t dst_ = sb_ + r_ * ROWB + c_ * 16;                               \
        asm volatile("cp.async.cg.shared.global [%0], [%1], 16;"                 \
                     :: "r"(dst_), "l"(src_));                                   \
    }                                                                            \
    _Pragma("unroll")                                                            \
    for (int j_ = 0; j_ < 4; j_++) {                                             \
        int t_ = tid + j_ * 256;                                                 \
        int r_ = t_ >> 3, c_ = t_ & 7;                                           \
        const __half* src_ = B + (size_t)(tn0 + r_) * EMBED + kc0_ + c_*8;       \
        uint32_t dst_ = sb_ + A_BYTES + r_ * ROWB + c_ * 16;                     \
        asm volatile("cp.async.cg.shared.global [%0], [%1], 16;"                 \
                     :: "r"(dst_), "l"(src_));                                   \
    }                                                                            \
    asm volatile("cp.async.commit_group;" ::: "memory");                         \
} while (0)

#define LOAD_FRAGS(buf, sb, ks) do {                                             \
    _Pragma("unroll")                                                            \
    for (int mi_ = 0; mi_ < 4; mi_++)                                            \
        LDSM_X4(aF[buf][mi_], (sb) + aoff[mi_] + (ks) * 32);                     \
    _Pragma("unroll")                                                            \
    for (int nj_ = 0; nj_ < 2; nj_++)                                            \
        LDSM_X4(bF[buf][nj_], (sb) + boff[nj_] + (ks) * 32);                     \
} while (0)

#define MMA_BLOCK(buf) do {                                                      \
    _Pragma("unroll")                                                            \
    for (int mi_ = 0; mi_ < 4; mi_++)                                            \
        _Pragma("unroll")                                                        \
        for (int n8_ = 0; n8_ < 4; n8_++)                                        \
            MMA16816(acc[mi_][n8_], aF[buf][mi_],                                \
                     bF[buf][n8_ >> 1][n8_ & 1],                                 \
                     bF[buf][n8_ >> 1][2 + (n8_ & 1)]);                          \
} while (0)

    uint32_t aF[2][4][4], bF[2][2][4];

    LOAD_CHUNK(0);
    LOAD_CHUNK(1);
    asm volatile("cp.async.wait_group 1;" ::: "memory");
    __syncthreads();
    LOAD_FRAGS(0, sbase0, 0);

    for (int i = 0; i < nchunk; i++) {
        const uint32_t sb = sbase0 + (i % 3) * STAGE_BYTES;

        if (i + 2 < nchunk) LOAD_CHUNK(i + 2);

        LOAD_FRAGS(1, sb, 1);
        MMA_BLOCK(0);
        LOAD_FRAGS(0, sb, 2);
        MMA_BLOCK(1);
        LOAD_FRAGS(1, sb, 3);
        MMA_BLOCK(0);

        if (i + 1 < nchunk) {
            asm volatile("cp.async.wait_group 1;" ::: "memory");
            __syncthreads();
            LOAD_FRAGS(0, sbase0 + ((i + 1) % 3) * STAGE_BYTES, 0);
        }

        MMA_BLOCK(1);   // ks3
    }
#undef LOAD_CHUNK
#undef LOAD_FRAGS
#undef MMA_BLOCK

    const int qr = lane >> 2;
    const int qc = (lane & 3) * 2;
#pragma unroll
    for (int mi = 0; mi < 4; mi++) {
        int row = tm0 + warp_m * 64 + mi * 16 + qr;
#pragma unroll
        for (int n8 = 0; n8 < 4; n8++) {
            int col = tn0 + warp_n * 32 + n8 * 8 + qc;
            float b0 = __ldg(bias + col);
            float b1 = __ldg(bias + col + 1);
            if (MODE == 0) {
                *(uint32_t*)(C + (size_t)row * EMBED + col) =
                    packh((acc[mi][n8][0] + b0) * scale,
                          (acc[mi][n8][1] + b1) * scale);
                *(uint32_t*)(C + (size_t)(row + 8) * EMBED + col) =
                    packh((acc[mi][n8][2] + b0) * scale,
                          (acc[mi][n8][3] + b1) * scale);
            } else {
                float2 o0 = { acc[mi][n8][0] + b0, acc[mi][n8][1] + b1 };
                float2 o1 = { acc[mi][n8][2] + b0, acc[mi][n8][3] + b1 };
                *(float2*)(Cf + (size_t)row * EMBED + col) = o0;
                *(float2*)(Cf + (size_t)(row + 8) * EMBED + col) = o1;
            }
        }
    }
}

// ---------------------------------------------------------------------------
// Tensor-core causal flash attention (fp16), max-free softmax,
// software-pipelined K/V fragment loads (double-buffered across MMA iters).
// ---------------------------------------------------------------------------
#define AKV       64
#define AQ_BYTES  16384
#define ASTAGE    16384
#define ATTN_SMEM (AQ_BYTES + 2*ASTAGE) // 49152

__global__ __launch_bounds__(256, 2)
void attn_tc(const __half* __restrict__ Qg, const __half* __restrict__ Kg,
             const __half* __restrict__ Vg, __half* __restrict__ Ctx)
{
    extern __shared__ char smbuf[];
    const uint32_t sbase = smem_u32(smbuf);
    const int tid  = threadIdx.x;
    const int lane = tid & 31;
    const int w    = tid >> 5;
    const int qt   = gridDim.x - 1 - blockIdx.x;
    const int bh   = blockIdx.y;
    const int b    = bh >> 5;
    const int h    = bh & 31;
    const int q0   = qt * 128;

    const size_t rowbase = (size_t)(b * SEQ);
    const __half* Qb = Qg + (rowbase + q0) * EMBED + h * HD;
    const __half* Kb = Kg + rowbase * EMBED + h * HD;
    const __half* Vb = Vg + rowbase * EMBED + h * HD;

#pragma unroll
    for (int t = 0; t < 4; t++) {
        int task = tid + t * 256;
        int r = task >> 3, c = task & 7;
        uint32_t dst = sbase + SWZ(r * 128 + c * 16);
        const __half* src = Qb + (size_t)r * EMBED + c * 8;
        asm volatile("cp.async.cg.shared.global [%0], [%1], 16;"
                     :: "r"(dst), "l"(src));
    }

#define LOADKV(jt_, st_) do {                                                     \
    uint32_t sb_ = sbase + AQ_BYTES + (st_) * ASTAGE;                             \
    _Pragma("unroll")                                                             \
    for (int t_ = 0; t_ < 4; t_++) {                                              \
        int task_ = tid + t_ * 256;                                               \
        int arr_  = task_ >> 9;                                                   \
        int idx_  = task_ & 511;                                                  \
        int r_ = idx_ >> 3, c_ = idx_ & 7;                                        \
        const __half* s_ = (arr_ == 0 ? Kb : Vb)                                  \
                           + (size_t)((jt_) * AKV + r_) * EMBED + c_ * 8;         \
        uint32_t d_ = sb_ + arr_ * 8192 + SWZ(r_ * 128 + c_ * 16);                \
        asm volatile("cp.async.cg.shared.global [%0], [%1], 16;"                  \
                     :: "r"(d_), "l"(s_));                                        \
    }                                                                             \
    asm volatile("cp.async.commit_group;" ::: "memory");                          \
} while (0)

    LOADKV(0, 0);

    float l0 = 0.0f, l1 = 0.0f;
    float oacc[8][4];
#pragma unroll
    for (int j = 0; j < 8; j++)
#pragma unroll
        for (int e = 0; e < 4; e++) oacc[j][e] = 0.0f;
    uint32_t aq[4][4];

    const int la7 = lane & 7, lb3 = (lane >> 3) & 1, lb4 = (lane >> 4) & 1;
    const int qrow = w * 16 + la7 + lb3 * 8, qcolb = lb4 * 16;
    const int krow = la7 + lb4 * 8,          kcolb = lb3 * 16;
    const int vrow = la7 + lb3 * 8,          vcolb = lb4 * 16;
    const int wrow_min = q0 + w * 16;
    const int wrow_max = wrow_min + 15;
    const int ntiles = 2 * qt + 2;

#define KADDR(it) (kst + SWZ((((it) & 3) * 16 + krow) * 128 + ((it) >> 2) * 32 + kcolb))
#define VADDR(it) (kst + 8192 + SWZ((((it) >> 2) * 16 + vrow) * 128 + ((it) & 3) * 32 + vcolb))

    for (int jt = 0; jt < ntiles; jt++) {
        if (jt + 1 < ntiles) {
            LOADKV(jt + 1, (jt + 1) & 1);
            asm volatile("cp.async.wait_group 1;" ::: "memory");
        } else {
            asm volatile("cp.async.wait_group 0;" ::: "memory");
        }
        __syncthreads();

        if (jt == 0) {
#pragma unroll
            for (int ks = 0; ks < 4; ks++)
                LDSM_X4(aq[ks], sbase + SWZ(qrow * 128 + ks * 32 + qcolb));
        }

        const uint32_t kst = sbase + AQ_BYTES + (jt & 1) * ASTAGE;
        if (jt * AKV <= wrow_max) {
            // ---- S = Q K^T, pipelined K-fragment loads ----
            float sa[8][4];
#pragma unroll
            for (int j = 0; j < 8; j++)
#pragma unroll
                for (int e = 0; e < 4; e++) sa[j][e] = 0.0f;

            {
                uint32_t kf[2][4];
                LDSM_X4(kf[0], KADDR(0));
#pragma unroll
                for (int it = 0; it < 16; it++) {
                    if (it < 15) LDSM_X4(kf[(it + 1) & 1], KADDR(it + 1));
                    const int ks = it >> 2, jp = it & 3;
                    MMA16816(sa[2 * jp],     aq[ks], kf[it & 1][0], kf[it & 1][1]);
                    MMA16816(sa[2 * jp + 1], aq[ks], kf[it & 1][2], kf[it & 1][3]);
                }
            }

            if (jt * AKV + 63 > wrow_min) {
#pragma unroll
                for (int j = 0; j < 8; j++) {
                    int colb = jt * AKV + j * 8 + 2 * (lane & 3);
                    int r0g  = wrow_min + (lane >> 2);
#pragma unroll
                    for (int e = 0; e < 4; e++) {
                        int col = colb + (e & 1);
                        int row = r0g + (e >> 1) * 8;
                        if (col > row) sa[j][e] = -1e30f;
                    }
                }
            }

            // ---- max-free softmax ----
            float rs0 = 0.0f, rs1 = 0.0f;
#pragma unroll
            for (int j = 0; j < 8; j++) {
                sa[j][0] = __expf(sa[j][0]);
                sa[j][1] = __expf(sa[j][1]);
                sa[j][2] = __expf(sa[j][2]);
                sa[j][3] = __expf(sa[j][3]);
                rs0 += sa[j][0] + sa[j][1];
                rs1 += sa[j][2] + sa[j][3];
            }
            rs0 += __shfl_xor_sync(0xffffffffu, rs0, 1);
            rs0 += __shfl_xor_sync(0xffffffffu, rs0, 2);
            rs1 += __shfl_xor_sync(0xffffffffu, rs1, 1);
            rs1 += __shfl_xor_sync(0xffffffffu, rs1, 2);
            l0 += rs0;
            l1 += rs1;

            // ---- pre-pack P fragments, then pipelined PV ----
            uint32_t pa[4][4];
#pragma unroll
            for (int t = 0; t < 4; t++) {
                pa[t][0] = packh(sa[2*t][0],   sa[2*t][1]);
                pa[t][1] = packh(sa[2*t][2],   sa[2*t][3]);
                pa[t][2] = packh(sa[2*t+1][0], sa[2*t+1][1]);
                pa[t][3] = packh(sa[2*t+1][2], sa[2*t+1][3]);
            }
            {
                uint32_t vF[2][4];
                LDSM_X4T(vF[0], VADDR(0));
#pragma unroll
                for (int it = 0; it < 16; it++) {
                    if (it < 15) LDSM_X4T(vF[(it + 1) & 1], VADDR(it + 1));
                    const int t = it >> 2, gg = it & 3;
                    MMA16816(oacc[2*gg],   pa[t], vF[it & 1][0], vF[it & 1][1]);
                    MMA16816(oacc[2*gg+1], pa[t], vF[it & 1][2], vF[it & 1][3]);
                }
            }
        }
        __syncthreads();
    }
#undef LOADKV
#undef KADDR
#undef VADDR

    float inv0 = 1.0f / l0, inv1 = 1.0f / l1;
    size_t grow0 = rowbase + q0 + w * 16 + (lane >> 2);
    __half* base0 = Ctx + grow0 * EMBED + h * HD + 2 * (lane & 3);
    __half* base1 = base0 + (size_t)8 * EMBED;
#pragma unroll
    for (int j = 0; j < 8; j++) {
        *(uint32_t*)(base0 + j * 8) = packh(oacc[j][0] * inv0, oacc[j][1] * inv0);
        *(uint32_t*)(base1 + j * 8) = packh(oacc[j][2] * inv1, oacc[j][3] * inv1);
    }
}

// ---------------------------------------------------------------------------
extern "C" void kernel_launch(void* const* d_in, const int* in_sizes, int n_in,
                              void* d_out, int out_size)
{
    const float* x  = (const float*)d_in[0];
    const float* Wq = (const float*)d_in[1];
    const float* bq = (const float*)d_in[2];
    const float* Wk = (const float*)d_in[3];
    const float* bk = (const float*)d_in[4];
    const float* Wv = (const float*)d_in[5];
    const float* bv = (const float*)d_in[6];
    const float* Wo = (const float*)d_in[7];
    const float* bo = (const float*)d_in[8];
    float* out = (float*)d_out;

    __half *xh, *qb, *kb, *vb, *ctx, *wq, *wk, *wv, *wo;
    cudaGetSymbolAddress((void**)&xh,  g_xh);
    cudaGetSymbolAddress((void**)&qb,  g_qb);
    cudaGetSymbolAddress((void**)&kb,  g_kb);
    cudaGetSymbolAddress((void**)&vb,  g_vb);
    cudaGetSymbolAddress((void**)&ctx, g_ctx);
    cudaGetSymbolAddress((void**)&wq,  g_wq);
    cudaGetSymbolAddress((void**)&wk,  g_wk);
    cudaGetSymbolAddress((void**)&wv,  g_wv);
    cudaGetSymbolAddress((void**)&wo,  g_wo);

    cudaFuncSetAttribute(attn_tc, cudaFuncAttributeMaxDynamicSharedMemorySize,
                         ATTN_SMEM);
    cudaFuncSetAttribute(gemm_tpl<0>, cudaFuncAttributeMaxDynamicSharedMemorySize,
                         GSMEM);
    cudaFuncSetAttribute(gemm_tpl<1>, cudaFuncAttributeMaxDynamicSharedMemorySize,
                         GSMEM);

    conv_all<<<(CONV_TASKS + 255) / 256, 256>>>(x, Wq, Wk, Wv, Wo,
                                                xh, wq, wk, wv, wo);

    dim3 qkvgrid(EMBED / TN, MROWS / TM, 3);     // (16, 32, 3)
    gemm_tpl<0><<<qkvgrid, 256, GSMEM>>>(xh, wq, wk, wv, bq, bk, bv,
                                         qb, kb, vb, nullptr);

    dim3 agrid(SEQ / 128, BATCH * NHEAD);        // (16, 64)
    attn_tc<<<agrid, 256, ATTN_SMEM>>>(qb, kb, vb, ctx);

    dim3 ogrid(EMBED / TN, MROWS / TM);          // (16, 32)
    gemm_tpl<1><<<ogrid, 256, GSMEM>>>(ctx, wo, nullptr, nullptr, bo, nullptr,
                                       nullptr, nullptr, nullptr, nullptr, out);
}

// round 16
// speedup vs baseline: 1.1506x; 1.0435x over previous
#include <cuda_runtime.h>
#include <cuda_fp16.h>
#include <cstdint>

#define EMBED   2048
#define NHEAD   32
#define HD      64
#define BATCH   2
#define SEQ     2048
#define MROWS   (BATCH*SEQ)      // 4096
#define QSCALE  (1.44269504088896f / 128.0f)   // log2(e) * (1/sqrt(64)) * (1/16)

// --- GEMM tiling: CTA 128x128, 8 warps (2x4), warp tile 64x32 ---
#define TM      128
#define TN      128
#define KC      64
#define ROWB    144
#define A_BYTES (TM*ROWB)        // 18432
#define B_BYTES (TN*ROWB)        // 18432
#define STAGE_BYTES (A_BYTES + B_BYTES)   // 36864
#define GSMEM   (3*STAGE_BYTES)           // 110592 (2 CTAs/SM: 216KB)

// Scratch (device globals: no runtime allocation allowed)
__device__ __align__(16) __half g_xh[(size_t)MROWS*EMBED];    // x fp16
__device__ __align__(16) __half g_qb[(size_t)MROWS*EMBED];    // Q fp16, pre-scaled log2e/128
__device__ __align__(16) __half g_kb[(size_t)MROWS*EMBED];    // K fp16
__device__ __align__(16) __half g_vb[(size_t)MROWS*EMBED];    // V fp16
__device__ __align__(16) __half g_ctx[(size_t)MROWS*EMBED];   // ctx fp16 (from attn)
__device__ __align__(16) __half g_wq[(size_t)EMBED*EMBED];
__device__ __align__(16) __half g_wk[(size_t)EMBED*EMBED];
__device__ __align__(16) __half g_wv[(size_t)EMBED*EMBED];
__device__ __align__(16) __half g_wo[(size_t)EMBED*EMBED];

// ---------------------------------------------------------------------------
__device__ __forceinline__ uint32_t smem_u32(const void* p) {
    uint32_t a;
    asm("{ .reg .u64 t; cvta.to.shared.u64 t, %1; cvt.u32.u64 %0, t; }"
        : "=r"(a) : "l"(p));
    return a;
}
#define SWZ(x) ((x) ^ (((x) >> 3) & 0x70))

#define LDSM_X4(r, addr) \
    asm volatile("ldmatrix.sync.aligned.m8n8.x4.shared.b16 {%0,%1,%2,%3}, [%4];" \
        : "=r"((r)[0]), "=r"((r)[1]), "=r"((r)[2]), "=r"((r)[3]) : "r"(addr))
#define LDSM_X4T(r, addr) \
    asm volatile("ldmatrix.sync.aligned.m8n8.x4.trans.shared.b16 {%0,%1,%2,%3}, [%4];" \
        : "=r"((r)[0]), "=r"((r)[1]), "=r"((r)[2]), "=r"((r)[3]) : "r"(addr))

#define MMA16816(d, a, b0, b1) \
    asm volatile("mma.sync.aligned.m16n8k16.row.col.f32.f16.f16.f32 " \
        "{%0,%1,%2,%3}, {%4,%5,%6,%7}, {%8,%9}, {%0,%1,%2,%3};" \
        : "+f"((d)[0]), "+f"((d)[1]), "+f"((d)[2]), "+f"((d)[3]) \
        : "r"((a)[0]), "r"((a)[1]), "r"((a)[2]), "r"((a)[3]), "r"(b0), "r"(b1))

__device__ __forceinline__ uint32_t packh(float x, float y) {
    __half2 t = __floats2half2_rn(x, y);
    return *reinterpret_cast<uint32_t*>(&t);
}
__device__ __forceinline__ uint32_t ex2h2(uint32_t v) {
    uint32_t o;
    asm("ex2.approx.f16x2 %0, %1;" : "=r"(o) : "r"(v));
    return o;
}

// ---------------------------------------------------------------------------
// Fused fp32 -> fp16 conversion of x + 4 weights (float4 granularity).
// ---------------------------------------------------------------------------
#define XT4 ((MROWS*EMBED)/4)           // 2097152
#define WT4 ((EMBED*EMBED)/4)           // 1048576
#define CONV_TASKS (XT4 + 4*WT4)        // 6291456

__global__ void conv_all(const float* __restrict__ x,
                         const float* __restrict__ wq, const float* __restrict__ wk,
                         const float* __restrict__ wv, const float* __restrict__ wo,
                         __half* __restrict__ xh,
                         __half* __restrict__ oq, __half* __restrict__ ok,
                         __half* __restrict__ ov, __half* __restrict__ oo)
{
    int idx = blockIdx.x * 256 + threadIdx.x;
    if (idx >= CONV_TASKS) return;
    const float* src; __half* dst; size_t rel;
    if (idx < XT4) {
        src = x; dst = xh; rel = (size_t)idx;
    } else {
        int j = idx - XT4;
        int seg = j >> 20;                 // WT4 = 1<<20
        rel = (size_t)(j & (WT4 - 1));
        src = (seg == 0) ? wq : (seg == 1) ? wk : (seg == 2) ? wv : wo;
        dst = (seg == 0) ? oq : (seg == 1) ? ok : (seg == 2) ? ov : oo;
    }
    float4 v = *(const float4*)(src + rel * 4);
    uint2 o;
    o.x = packh(v.x, v.y);
    o.y = packh(v.z, v.w);
    *(uint2*)(dst + rel * 4) = o;
}

// ---------------------------------------------------------------------------
// HMMA fp16 GEMM (R12 config, unchanged):
//   MODE 0: fused QKV (z selects weight/bias/output, fp16 out, Q scaled)
//   MODE 1: out-proj (fp32 out)
// ---------------------------------------------------------------------------
template<int MODE>
__global__ __launch_bounds__(256, 2)
void gemm_tpl(const __half* __restrict__ A,
              const __half* __restrict__ B0, const __half* __restrict__ B1,
              const __half* __restrict__ B2,
              const float* __restrict__ bi0, const float* __restrict__ bi1,
              const float* __restrict__ bi2,
              __half* __restrict__ C0, __half* __restrict__ C1,
              __half* __restrict__ C2, float* __restrict__ Cf)
{
    const int z = (MODE == 0) ? blockIdx.z : 0;
    const __half* B   = (z == 0) ? B0 : (z == 1) ? B1 : B2;
    const float* bias = (z == 0) ? bi0 : (z == 1) ? bi1 : bi2;
    __half* C         = (z == 0) ? C0 : (z == 1) ? C1 : C2;
    const float scale = (MODE == 0 && z == 0) ? QSCALE : 1.0f;

    extern __shared__ char dsm[];
    const uint32_t sbase0 = smem_u32(dsm);
    const int tid    = threadIdx.x;
    const int warp   = tid >> 5;
    const int lane   = tid & 31;
    const int warp_m = warp >> 2;
    const int warp_n = warp & 3;
    const int tm0    = blockIdx.y * TM;
    const int tn0    = blockIdx.x * TN;
    const int nchunk = EMBED / KC;       // 32

    const int g  = lane >> 3;
    const int lr = lane & 7;
    uint32_t aoff[4], boff[2];
#pragma unroll
    for (int mi = 0; mi < 4; mi++)
        aoff[mi] = (uint32_t)((warp_m * 64 + mi * 16 + (g & 1) * 8 + lr) * ROWB
                              + (g >> 1) * 16);
#pragma unroll
    for (int nj = 0; nj < 2; nj++)
        boff[nj] = (uint32_t)(A_BYTES
                              + (warp_n * 32 + nj * 16 + (g & 1) * 8 + lr) * ROWB
                              + (g >> 1) * 16);

    float acc[4][4][4];
#pragma unroll
    for (int mi = 0; mi < 4; mi++)
#pragma unroll
        for (int n8 = 0; n8 < 4; n8++)
#pragma unroll
            for (int e = 0; e < 4; e++) acc[mi][n8][e] = 0.0f;

#define LOAD_CHUNK(ci) do {                                                      \
    uint32_t sb_ = sbase0 + ((ci) % 3) * STAGE_BYTES;                            \
    int kc0_ = (ci) * KC;                                                        \
    _Pragma("unroll")                                                            \
    for (int j_ = 0; j_ < 4; j_++) {                                             \
        int t_ = tid + j_ * 256;                                                 \
        int r_ = t_ >> 3, c_ = t_ & 7;                                           \
        const __half* src_ = A + (size_t)(tm0 + r_) * EMBED + kc0_ + c_*8;       \
        uint32_t dst_ = sb_ + r_ * ROWB + c_ * 16;                               \
        asm volatile("cp.async.cg.shared.global [%0], [%1], 16;"                 \
                     :: "r"(dst_), "l"(src_));                                   \
    }                                                                            \
    _Pragma("unroll")                                                            \
    for (int j_ = 0; j_ < 4; j_++) {                                             \
        int t_ = tid + j_ * 256;                                                 \
        int r_ = t_ >> 3, c_ = t_ & 7;                                           \
        const __half* src_ = B + (size_t)(tn0 + r_) * EMBED + kc0_ + c_*8;       \
        uint32_t dst_ = sb_ + A_BYTES + r_ * ROWB + c_ * 16;                     \
        asm volatile("cp.async.cg.shared.global [%0], [%1], 16;"                 \
                     :: "r"(dst_), "l"(src_));                                   \
    }                                                                            \
    asm volatile("cp.async.commit_group;" ::: "memory");                         \
} while (0)

#define LOAD_FRAGS(buf, sb, ks) do {                                             \
    _Pragma("unroll")                                                            \
    for (int mi_ = 0; mi_ < 4; mi_++)                                            \
        LDSM_X4(aF[buf][mi_], (sb) + aoff[mi_] + (ks) * 32);                     \
    _Pragma("unroll")                                                            \
    for (int nj_ = 0; nj_ < 2; nj_++)                                            \
        LDSM_X4(bF[buf][nj_], (sb) + boff[nj_] + (ks) * 32);                     \
} while (0)

#define MMA_BLOCK(buf) do {                                                      \
    _Pragma("unroll")                                                            \
    for (int mi_ = 0; mi_ < 4; mi_++)                                            \
        _Pragma("unroll")                                                        \
        for (int n8_ = 0; n8_ < 4; n8_++)                                        \
            MMA16816(acc[mi_][n8_], aF[buf][mi_],                                \
                     bF[buf][n8_ >> 1][n8_ & 1],                                 \
                     bF[buf][n8_ >> 1][2 + (n8_ & 1)]);                          \
} while (0)

    uint32_t aF[2][4][4], bF[2][2][4];

    LOAD_CHUNK(0);
    LOAD_CHUNK(1);
    asm volatile("cp.async.wait_group 1;" ::: "memory");
    __syncthreads();
    LOAD_FRAGS(0, sbase0, 0);

    for (int i = 0; i < nchunk; i++) {
        const uint32_t sb = sbase0 + (i % 3) * STAGE_BYTES;

        if (i + 2 < nchunk) LOAD_CHUNK(i + 2);

        LOAD_FRAGS(1, sb, 1);
        MMA_BLOCK(0);
        LOAD_FRAGS(0, sb, 2);
        MMA_BLOCK(1);
        LOAD_FRAGS(1, sb, 3);
        MMA_BLOCK(0);

        if (i + 1 < nchunk) {
            asm volatile("cp.async.wait_group 1;" ::: "memory");
            __syncthreads();
            LOAD_FRAGS(0, sbase0 + ((i + 1) % 3) * STAGE_BYTES, 0);
        }

        MMA_BLOCK(1);   // ks3
    }
#undef LOAD_CHUNK
#undef LOAD_FRAGS
#undef MMA_BLOCK

    const int qr = lane >> 2;
    const int qc = (lane & 3) * 2;
#pragma unroll
    for (int mi = 0; mi < 4; mi++) {
        int row = tm0 + warp_m * 64 + mi * 16 + qr;
#pragma unroll
        for (int n8 = 0; n8 < 4; n8++) {
            int col = tn0 + warp_n * 32 + n8 * 8 + qc;
            float b0 = __ldg(bias + col);
            float b1 = __ldg(bias + col + 1);
            if (MODE == 0) {
                *(uint32_t*)(C + (size_t)row * EMBED + col) =
                    packh((acc[mi][n8][0] + b0) * scale,
                          (acc[mi][n8][1] + b1) * scale);
                *(uint32_t*)(C + (size_t)(row + 8) * EMBED + col) =
                    packh((acc[mi][n8][2] + b0) * scale,
                          (acc[mi][n8][3] + b1) * scale);
            } else {
                float2 o0 = { acc[mi][n8][0] + b0, acc[mi][n8][1] + b1 };
                float2 o1 = { acc[mi][n8][2] + b0, acc[mi][n8][3] + b1 };
                *(float2*)(Cf + (size_t)row * EMBED + col) = o0;
                *(float2*)(Cf + (size_t)(row + 8) * EMBED + col) = o1;
            }
        }
    }
}

// ---------------------------------------------------------------------------
// Tensor-core causal flash attention (fp16).
// Base-2 softmax: Q pre-scaled by log2e/128, P = 2^S via ex2.approx.f16x2.
// Row sums computed by a ones-column MMA (consistent with fp16 P).
// ---------------------------------------------------------------------------
#define AKV       64
#define AQ_BYTES  16384
#define ASTAGE    16384
#define ATTN_SMEM (AQ_BYTES + 2*ASTAGE) // 49152

__global__ __launch_bounds__(256, 2)
void attn_tc(const __half* __restrict__ Qg, const __half* __restrict__ Kg,
             const __half* __restrict__ Vg, __half* __restrict__ Ctx)
{
    extern __shared__ char smbuf[];
    const uint32_t sbase = smem_u32(smbuf);
    const int tid  = threadIdx.x;
    const int lane = tid & 31;
    const int w    = tid >> 5;
    const int qt   = gridDim.x - 1 - blockIdx.x;
    const int bh   = blockIdx.y;
    const int b    = bh >> 5;
    const int h    = bh & 31;
    const int q0   = qt * 128;

    const size_t rowbase = (size_t)(b * SEQ);
    const __half* Qb = Qg + (rowbase + q0) * EMBED + h * HD;
    const __half* Kb = Kg + rowbase * EMBED + h * HD;
    const __half* Vb = Vg + rowbase * EMBED + h * HD;

#pragma unroll
    for (int t = 0; t < 4; t++) {
        int task = tid + t * 256;
        int r = task >> 3, c = task & 7;
        uint32_t dst = sbase + SWZ(r * 128 + c * 16);
        const __half* src = Qb + (size_t)r * EMBED + c * 8;
        asm volatile("cp.async.cg.shared.global [%0], [%1], 16;"
                     :: "r"(dst), "l"(src));
    }

#define LOADKV(jt_, st_) do {                                                     \
    uint32_t sb_ = sbase + AQ_BYTES + (st_) * ASTAGE;                             \
    _Pragma("unroll")                                                             \
    for (int t_ = 0; t_ < 4; t_++) {                                              \
        int task_ = tid + t_ * 256;                                               \
        int arr_  = task_ >> 9;                                                   \
        int idx_  = task_ & 511;                                                  \
        int r_ = idx_ >> 3, c_ = idx_ & 7;                                        \
        const __half* s_ = (arr_ == 0 ? Kb : Vb)                                  \
                           + (size_t)((jt_) * AKV + r_) * EMBED + c_ * 8;         \
        uint32_t d_ = sb_ + arr_ * 8192 + SWZ(r_ * 128 + c_ * 16);                \
        asm volatile("cp.async.cg.shared.global [%0], [%1], 16;"                  \
                     :: "r"(d_), "l"(s_));                                        \
    }                                                                             \
    asm volatile("cp.async.commit_group;" ::: "memory");                          \
} while (0)

    LOADKV(0, 0);

    float oacc[8][4];
#pragma unroll
    for (int j = 0; j < 8; j++)
#pragma unroll
        for (int e = 0; e < 4; e++) oacc[j][e] = 0.0f;
    float lacc[4] = {0.0f, 0.0f, 0.0f, 0.0f};
    uint32_t aq[4][4];
    const uint32_t one2 = packh(1.0f, 1.0f);

    const int la7 = lane & 7, lb3 = (lane >> 3) & 1, lb4 = (lane >> 4) & 1;
    const int qrow = w * 16 + la7 + lb3 * 8, qcolb = lb4 * 16;
    const int krow = la7 + lb4 * 8,          kcolb = lb3 * 16;
    const int vrow = la7 + lb3 * 8,          vcolb = lb4 * 16;
    const int wrow_min = q0 + w * 16;
    const int wrow_max = wrow_min + 15;
    const int ntiles = 2 * qt + 2;

#define KADDR(it) (kst + SWZ((((it) & 3) * 16 + krow) * 128 + ((it) >> 2) * 32 + kcolb))
#define VADDR(it) (kst + 8192 + SWZ((((it) >> 2) * 16 + vrow) * 128 + ((it) & 3) * 32 + vcolb))

    for (int jt = 0; jt < ntiles; jt++) {
        if (jt + 1 < ntiles) {
            LOADKV(jt + 1, (jt + 1) & 1);
            asm volatile("cp.async.wait_group 1;" ::: "memory");
        } else {
            asm volatile("cp.async.wait_group 0;" ::: "memory");
        }
        __syncthreads();

        if (jt == 0) {
#pragma unroll
            for (int ks = 0; ks < 4; ks++)
                LDSM_X4(aq[ks], sbase + SWZ(qrow * 128 + ks * 32 + qcolb));
        }

        const uint32_t kst = sbase + AQ_BYTES + (jt & 1) * ASTAGE;
        if (jt * AKV <= wrow_max) {
            // ---- S = Q K^T (log2-scaled), pipelined K-fragment loads ----
            float sa[8][4];
#pragma unroll
            for (int j = 0; j < 8; j++)
#pragma unroll
                for (int e = 0; e < 4; e++) sa[j][e] = 0.0f;

            {
                uint32_t kf[2][4];
                LDSM_X4(kf[0], KADDR(0));
#pragma unroll
                for (int it = 0; it < 16; it++) {
                    if (it < 15) LDSM_X4(kf[(it + 1) & 1], KADDR(it + 1));
                    const int ks = it >> 2, jp = it & 3;
                    MMA16816(sa[2 * jp],     aq[ks], kf[it & 1][0], kf[it & 1][1]);
                    MMA16816(sa[2 * jp + 1], aq[ks], kf[it & 1][2], kf[it & 1][3]);
                }
            }

            // causal mask (finite large-negative: 2^-30000 -> 0 in fp16)
            if (jt * AKV + 63 > wrow_min) {
#pragma unroll
                for (int j = 0; j < 8; j++) {
                    int colb = jt * AKV + j * 8 + 2 * (lane & 3);
                    int r0g  = wrow_min + (lane >> 2);
#pragma unroll
                    for (int e = 0; e < 4; e++) {
                        int col = colb + (e & 1);
                        int row = r0g + (e >> 1) * 8;
                        if (col > row) sa[j][e] = -30000.0f;
                    }
                }
            }

            // ---- P = 2^S in fp16x2 (these ARE the MMA A-fragments) ----
            uint32_t pa[4][4];
#pragma unroll
            for (int j = 0; j < 8; j++) {
                uint32_t e01 = ex2h2(packh(sa[j][0], sa[j][1]));
                uint32_t e23 = ex2h2(packh(sa[j][2], sa[j][3]));
                pa[j >> 1][(j & 1) * 2 + 0] = e01;
                pa[j >> 1][(j & 1) * 2 + 1] = e23;
            }

            // ---- pipelined PV + ones-column row-sum MMA ----
            {
                uint32_t vF[2][4];
                LDSM_X4T(vF[0], VADDR(0));
#pragma unroll
                for (int it = 0; it < 16; it++) {
                    if (it < 15) LDSM_X4T(vF[(it + 1) & 1], VADDR(it + 1));
                    const int t = it >> 2, gg = it & 3;
                    if (gg == 0) MMA16816(lacc, pa[t], one2, one2);
                    MMA16816(oacc[2*gg],   pa[t], vF[it & 1][0], vF[it & 1][1]);
                    MMA16816(oacc[2*gg+1], pa[t], vF[it & 1][2], vF[it & 1][3]);
                }
            }
        }
        __syncthreads();
    }
#undef LOADKV
#undef KADDR
#undef VADDR

    // lacc[0] = rowsum(row), lacc[2] = rowsum(row+8) — no shuffles needed
    float inv0 = 1.0f / lacc[0], inv1 = 1.0f / lacc[2];
    size_t grow0 = rowbase + q0 + w * 16 + (lane >> 2);
    __half* base0 = Ctx + grow0 * EMBED + h * HD + 2 * (lane & 3);
    __half* base1 = base0 + (size_t)8 * EMBED;
#pragma unroll
    for (int j = 0; j < 8; j++) {
        *(uint32_t*)(base0 + j * 8) = packh(oacc[j][0] * inv0, oacc[j][1] * inv0);
        *(uint32_t*)(base1 + j * 8) = packh(oacc[j][2] * inv1, oacc[j][3] * inv1);
    }
}

// ---------------------------------------------------------------------------
extern "C" void kernel_launch(void* const* d_in, const int* in_sizes, int n_in,
                              void* d_out, int out_size)
{
    const float* x  = (const float*)d_in[0];
    const float* Wq = (const float*)d_in[1];
    const float* bq = (const float*)d_in[2];
    const float* Wk = (const float*)d_in[3];
    const float* bk = (const float*)d_in[4];
    const float* Wv = (const float*)d_in[5];
    const float* bv = (const float*)d_in[6];
    const float* Wo = (const float*)d_in[7];
    const float* bo = (const float*)d_in[8];
    float* out = (float*)d_out;

    __half *xh, *qb, *kb, *vb, *ctx, *wq, *wk, *wv, *wo;
    cudaGetSymbolAddress((void**)&xh,  g_xh);
    cudaGetSymbolAddress((void**)&qb,  g_qb);
    cudaGetSymbolAddress((void**)&kb,  g_kb);
    cudaGetSymbolAddress((void**)&vb,  g_vb);
    cudaGetSymbolAddress((void**)&ctx, g_ctx);
    cudaGetSymbolAddress((void**)&wq,  g_wq);
    cudaGetSymbolAddress((void**)&wk,  g_wk);
    cudaGetSymbolAddress((void**)&wv,  g_wv);
    cudaGetSymbolAddress((void**)&wo,  g_wo);

    cudaFuncSetAttribute(attn_tc, cudaFuncAttributeMaxDynamicSharedMemorySize,
                         ATTN_SMEM);
    cudaFuncSetAttribute(gemm_tpl<0>, cudaFuncAttributeMaxDynamicSharedMemorySize,
                         GSMEM);
    cudaFuncSetAttribute(gemm_tpl<1>, cudaFuncAttributeMaxDynamicSharedMemorySize,
                         GSMEM);

    conv_all<<<(CONV_TASKS + 255) / 256, 256>>>(x, Wq, Wk, Wv, Wo,
                                                xh, wq, wk, wv, wo);

    dim3 qkvgrid(EMBED / TN, MROWS / TM, 3);     // (16, 32, 3)
    gemm_tpl<0><<<qkvgrid, 256, GSMEM>>>(xh, wq, wk, wv, bq, bk, bv,
                                         qb, kb, vb, nullptr);

    dim3 agrid(SEQ / 128, BATCH * NHEAD);        // (16, 64)
    attn_tc<<<agrid, 256, ATTN_SMEM>>>(qb, kb, vb, ctx);

    dim3 ogrid(EMBED / TN, MROWS / TM);          // (16, 32)
    gemm_tpl<1><<<ogrid, 256, GSMEM>>>(ctx, wo, nullptr, nullptr, bo, nullptr,
                                       nullptr, nullptr, nullptr, nullptr, out);
}